// round 1
// baseline (speedup 1.0000x reference)
#include <cuda_runtime.h>

// QuantumLayer: 4-qubit, 5-layer StronglyEntangling circuit over B=262144.
// Strategy: the post-embedding circuit is a fixed 16x16 complex unitary U
// (depends only on `weights`). Kernel 1 (16 threads) builds U gate-by-gate.
// Kernel 2: per element, build the REAL product state s[16] from sincos(x/2),
// y = U*s (512 FFMA), p = |y|^2, signed sums -> <Z_w>.

#define TPB 256
#define EPT 2   // batch elements per thread (amortizes U loads)

__device__ float2 g_U[256];  // row-major U[i][j], complex

// ---------------------------------------------------------------------------
// Kernel 1: build the 16x16 circuit unitary. Thread j evolves basis column j.
// ---------------------------------------------------------------------------
__global__ void build_unitary_kernel(const float* __restrict__ weights) {
    const int j = threadIdx.x;
    if (j >= 16) return;
    float vr[16], vi[16];
#pragma unroll
    for (int i = 0; i < 16; ++i) { vr[i] = (i == j) ? 1.0f : 0.0f; vi[i] = 0.0f; }

#pragma unroll
    for (int l = 0; l < 5; ++l) {
        // --- Rot(phi, theta, omega) on each wire ---
#pragma unroll
        for (int w = 0; w < 4; ++w) {
            const float phi   = weights[(l * 4 + w) * 3 + 0];
            const float theta = weights[(l * 4 + w) * 3 + 1];
            const float omega = weights[(l * 4 + w) * 3 + 2];
            float sp, cp, sm2, cm2, st, ct;
            sincosf(0.5f * (phi + omega), &sp, &cp);   // ep = (cp, -sp)
            sincosf(0.5f * (phi - omega), &sm2, &cm2); // em = (cm2, sm2)
            sincosf(0.5f * theta, &st, &ct);
            const float r00r =  cp  * ct, r00i = -sp  * ct;
            const float r01r = -cm2 * st, r01i = -sm2 * st;
            const float r10r =  cm2 * st, r10i = -sm2 * st;
            const float r11r =  cp  * ct, r11i =  sp  * ct;
            const int m = 8 >> w;  // qubit 0 is the MSB of the state index
#pragma unroll
            for (int i = 0; i < 16; ++i) {
                if ((i & m) == 0) {
                    const int i1 = i | m;
                    const float ar = vr[i],  ai = vi[i];
                    const float br = vr[i1], bi = vi[i1];
                    vr[i]  = r00r*ar - r00i*ai + r01r*br - r01i*bi;
                    vi[i]  = r00r*ai + r00i*ar + r01r*bi + r01i*br;
                    vr[i1] = r10r*ar - r10i*ai + r11r*br - r11i*bi;
                    vi[i1] = r10r*ai + r10i*ar + r11r*bi + r11i*br;
                }
            }
        }
        // --- CNOT ring, range r = (l mod 3) + 1: out[c,t] = in[c, t^c] ---
        const int r = (l % 3) + 1;
#pragma unroll
        for (int w = 0; w < 4; ++w) {
            const int mc = 8 >> w;
            const int mt = 8 >> ((w + r) & 3);
#pragma unroll
            for (int i = 0; i < 16; ++i) {
                if ((i & mc) && (i & mt)) {  // each affected pair swapped once
                    const int i2 = i ^ mt;
                    float t;
                    t = vr[i]; vr[i] = vr[i2]; vr[i2] = t;
                    t = vi[i]; vi[i] = vi[i2]; vi[i2] = t;
                }
            }
        }
    }
#pragma unroll
    for (int i = 0; i < 16; ++i) g_U[i * 16 + j] = make_float2(vr[i], vi[i]);
}

// ---------------------------------------------------------------------------
// Kernel 2: batched y = U * s, probabilities, <Z_w>.
// ---------------------------------------------------------------------------
__global__ __launch_bounds__(TPB)
void qforward_kernel(const float4* __restrict__ x, float4* __restrict__ out, int B) {
    __shared__ float4 shU[128];  // 16 rows * 8 float4 (each float4 = 2 complex)
    if (threadIdx.x < 128)
        shU[threadIdx.x] = reinterpret_cast<const float4*>(g_U)[threadIdx.x];
    __syncthreads();

    const int base = blockIdx.x * (TPB * EPT) + threadIdx.x;

    float s[EPT][16];
    bool valid[EPT];
#pragma unroll
    for (int e = 0; e < EPT; ++e) {
        const int idx = base + e * TPB;
        valid[e] = (idx < B);
        const float4 xv = valid[e] ? x[idx] : make_float4(0.f, 0.f, 0.f, 0.f);
        float c0, s0, c1, s1, c2, s2, c3, s3;
        __sincosf(0.5f * xv.x, &s0, &c0);
        __sincosf(0.5f * xv.y, &s1, &c1);
        __sincosf(0.5f * xv.z, &s2, &c2);
        __sincosf(0.5f * xv.w, &s3, &c3);
        const float a0 = c0 * c1, a1 = c0 * s1, a2 = s0 * c1, a3 = s0 * s1;
        const float b0 = c2 * c3, b1 = c2 * s3, b2 = s2 * c3, b3 = s2 * s3;
        // index = q0*8 + q1*4 + q2*2 + q3
        s[e][ 0] = a0*b0; s[e][ 1] = a0*b1; s[e][ 2] = a0*b2; s[e][ 3] = a0*b3;
        s[e][ 4] = a1*b0; s[e][ 5] = a1*b1; s[e][ 6] = a1*b2; s[e][ 7] = a1*b3;
        s[e][ 8] = a2*b0; s[e][ 9] = a2*b1; s[e][10] = a2*b2; s[e][11] = a2*b3;
        s[e][12] = a3*b0; s[e][13] = a3*b1; s[e][14] = a3*b2; s[e][15] = a3*b3;
    }

    float z0[EPT], z1[EPT], z2[EPT], z3[EPT];
#pragma unroll
    for (int e = 0; e < EPT; ++e) { z0[e] = z1[e] = z2[e] = z3[e] = 0.f; }

#pragma unroll
    for (int i = 0; i < 16; ++i) {
        float yr[EPT], yi[EPT];
#pragma unroll
        for (int e = 0; e < EPT; ++e) { yr[e] = 0.f; yi[e] = 0.f; }
#pragma unroll
        for (int jv = 0; jv < 8; ++jv) {
            const float4 u = shU[i * 8 + jv];  // warp-uniform -> LDS broadcast
#pragma unroll
            for (int e = 0; e < EPT; ++e) {
                yr[e] = fmaf(u.x, s[e][2 * jv],     yr[e]);
                yi[e] = fmaf(u.y, s[e][2 * jv],     yi[e]);
                yr[e] = fmaf(u.z, s[e][2 * jv + 1], yr[e]);
                yi[e] = fmaf(u.w, s[e][2 * jv + 1], yi[e]);
            }
        }
#pragma unroll
        for (int e = 0; e < EPT; ++e) {
            const float p = yr[e] * yr[e] + yi[e] * yi[e];
            z0[e] += (i & 8) ? -p : p;
            z1[e] += (i & 4) ? -p : p;
            z2[e] += (i & 2) ? -p : p;
            z3[e] += (i & 1) ? -p : p;
        }
    }

#pragma unroll
    for (int e = 0; e < EPT; ++e) {
        const int idx = base + e * TPB;
        if (valid[e]) out[idx] = make_float4(z0[e], z1[e], z2[e], z3[e]);
    }
}

// ---------------------------------------------------------------------------
extern "C" void kernel_launch(void* const* d_in, const int* in_sizes, int n_in,
                              void* d_out, int out_size) {
    const float* x   = (const float*)d_in[0];
    const float* wts = (const float*)d_in[1];
    int bx = 0, bw = 1;
    if (n_in >= 2 && in_sizes[0] == 60) { bx = 1; bw = 0; }  // robustness to order
    x   = (const float*)d_in[bx];
    wts = (const float*)d_in[bw];
    const int B = in_sizes[bx] / 4;

    build_unitary_kernel<<<1, 32>>>(wts);
    const int grid = (B + TPB * EPT - 1) / (TPB * EPT);
    qforward_kernel<<<grid, TPB>>>((const float4*)x, (float4*)d_out, B);
}

// round 2
// speedup vs baseline: 1.0123x; 1.0123x over previous
#include <cuda_runtime.h>

// QuantumLayer: z_w(x) = s^T M_w s with M_w = Re(U^dag Z_w U) reduces to a
// 4-output trilinear polynomial over per-qubit features (1, cos x_i, sin x_i):
//   z_w = sum_{u,v} C[w][u][v] * p01[u] * p23[v],   (81 coeffs per output)
// Kernel 1 builds C (U -> M_w -> C). Kernel 2 evaluates with packed f32x2 FMA
// (outputs w0w1 / w2w3 packed), 180 FFMA2 per element.

#define TPB 256
#define EPT 2

typedef unsigned long long ull;

__device__ float4 g_C[81];   // [u*9+v] -> (C_w0, C_w1, C_w2, C_w3)

// ---------------------------------------------------------------------------
// packed f32x2 helpers
// ---------------------------------------------------------------------------
__device__ __forceinline__ ull pk2(float lo, float hi) {
    ull r; asm("mov.b64 %0,{%1,%2};" : "=l"(r) : "f"(lo), "f"(hi)); return r;
}
__device__ __forceinline__ void upk2(ull a, float& lo, float& hi) {
    asm("mov.b64 {%0,%1},%2;" : "=f"(lo), "=f"(hi) : "l"(a));
}
__device__ __forceinline__ ull fma2(ull a, ull b, ull c) {
    ull d; asm("fma.rn.f32x2 %0,%1,%2,%3;" : "=l"(d) : "l"(a), "l"(b), "l"(c)); return d;
}
__device__ __forceinline__ ull mul2(ull a, ull b) {
    ull d; asm("mul.rn.f32x2 %0,%1,%2;" : "=l"(d) : "l"(a), "l"(b)); return d;
}

// ---------------------------------------------------------------------------
// Kernel 1: weights -> U (16 thr) -> M_w (256 thr) -> C (81 thr). One block.
// ---------------------------------------------------------------------------
__global__ void build_coeff_kernel(const float* __restrict__ weights) {
    __shared__ float sUr[16][16], sUi[16][16];   // [row i][col j]
    __shared__ float sM[256 * 4];                // [(j*16+k)*4 + w]
    const int tid = threadIdx.x;

    // --- Stage 1: evolve basis column tid through the circuit ---
    if (tid < 16) {
        const int j = tid;
        float vr[16], vi[16];
#pragma unroll
        for (int i = 0; i < 16; ++i) { vr[i] = (i == j) ? 1.0f : 0.0f; vi[i] = 0.0f; }
#pragma unroll
        for (int l = 0; l < 5; ++l) {
#pragma unroll
            for (int w = 0; w < 4; ++w) {
                const float phi   = weights[(l * 4 + w) * 3 + 0];
                const float theta = weights[(l * 4 + w) * 3 + 1];
                const float omega = weights[(l * 4 + w) * 3 + 2];
                float sp, cp, sm2, cm2, st, ct;
                sincosf(0.5f * (phi + omega), &sp, &cp);
                sincosf(0.5f * (phi - omega), &sm2, &cm2);
                sincosf(0.5f * theta, &st, &ct);
                const float r00r =  cp  * ct, r00i = -sp  * ct;
                const float r01r = -cm2 * st, r01i = -sm2 * st;
                const float r10r =  cm2 * st, r10i = -sm2 * st;
                const float r11r =  cp  * ct, r11i =  sp  * ct;
                const int m = 8 >> w;
#pragma unroll
                for (int i = 0; i < 16; ++i) {
                    if ((i & m) == 0) {
                        const int i1 = i | m;
                        const float ar = vr[i],  ai = vi[i];
                        const float br = vr[i1], bi = vi[i1];
                        vr[i]  = r00r*ar - r00i*ai + r01r*br - r01i*bi;
                        vi[i]  = r00r*ai + r00i*ar + r01r*bi + r01i*br;
                        vr[i1] = r10r*ar - r10i*ai + r11r*br - r11i*bi;
                        vi[i1] = r10r*ai + r10i*ar + r11r*bi + r11i*br;
                    }
                }
            }
            const int r = (l % 3) + 1;
#pragma unroll
            for (int w = 0; w < 4; ++w) {
                const int mc = 8 >> w;
                const int mt = 8 >> ((w + r) & 3);
#pragma unroll
                for (int i = 0; i < 16; ++i) {
                    if ((i & mc) && (i & mt)) {
                        const int i2 = i ^ mt;
                        float t;
                        t = vr[i]; vr[i] = vr[i2]; vr[i2] = t;
                        t = vi[i]; vi[i] = vi[i2]; vi[i2] = t;
                    }
                }
            }
        }
#pragma unroll
        for (int i = 0; i < 16; ++i) { sUr[i][j] = vr[i]; sUi[i][j] = vi[i]; }
    }
    __syncthreads();

    // --- Stage 2: M_w[j][k] = sum_i sign_w(i) Re(conj U_ij * U_ik) ---
    if (tid < 256) {
        const int j = tid >> 4, k = tid & 15;
        float m0 = 0.f, m1 = 0.f, m2 = 0.f, m3 = 0.f;
#pragma unroll
        for (int i = 0; i < 16; ++i) {
            const float p = sUr[i][j] * sUr[i][k] + sUi[i][j] * sUi[i][k];
            m0 += (i & 8) ? -p : p;
            m1 += (i & 4) ? -p : p;
            m2 += (i & 2) ? -p : p;
            m3 += (i & 1) ? -p : p;
        }
        sM[tid * 4 + 0] = m0; sM[tid * 4 + 1] = m1;
        sM[tid * 4 + 2] = m2; sM[tid * 4 + 3] = m3;
    }
    __syncthreads();

    // --- Stage 3: C[w][t] = 1/16 * sum over 16 (j,k) combos with signs ---
    // Per qubit: t=0 (const): (0,0)+,(1,1)+ ; t=1 (cos): (0,0)+,(1,1)- ;
    //            t=2 (sin): (0,1)+,(1,0)+.
    if (tid < 81) {
        const int t0 = tid / 27, t1 = (tid / 9) % 3, t2 = (tid / 3) % 3, t3 = tid % 3;
        const int tt[4] = {t0, t1, t2, t3};
        float a0 = 0.f, a1 = 0.f, a2 = 0.f, a3 = 0.f;
#pragma unroll
        for (int b = 0; b < 16; ++b) {
            int j = 0, k = 0; float sgn = 1.0f;
#pragma unroll
            for (int q = 0; q < 4; ++q) {           // q=0 -> MSB of state index
                const int o = (b >> q) & 1;
                const int ti = tt[q];
                int jq, kq;
                if (ti == 2) { jq = o; kq = 1 - o; }
                else { jq = o; kq = o; if (ti == 1 && o) sgn = -sgn; }
                j = (j << 1) | jq;
                k = (k << 1) | kq;
            }
            const float* m = &sM[(j * 16 + k) * 4];
            a0 += sgn * m[0]; a1 += sgn * m[1];
            a2 += sgn * m[2]; a3 += sgn * m[3];
        }
        const int u = t0 * 3 + t1, v = t2 * 3 + t3;
        g_C[u * 9 + v] = make_float4(a0 * 0.0625f, a1 * 0.0625f,
                                     a2 * 0.0625f, a3 * 0.0625f);
    }
}

// ---------------------------------------------------------------------------
// Kernel 2: trilinear evaluation with packed outputs.
// ---------------------------------------------------------------------------
__global__ __launch_bounds__(TPB)
void qforward_kernel(const float4* __restrict__ x, float4* __restrict__ out, int B) {
    __shared__ __align__(16) ull shC[162];       // [uv][{w01, w23}]
    if (threadIdx.x < 81) {
        const float4 c = g_C[threadIdx.x];
        shC[2 * threadIdx.x]     = pk2(c.x, c.y);
        shC[2 * threadIdx.x + 1] = pk2(c.z, c.w);
    }
    __syncthreads();

    const int base = blockIdx.x * (TPB * EPT) + threadIdx.x;

    ull p01[EPT][9], p23[EPT][9];
    bool valid[EPT];
    const ull ONE = pk2(1.0f, 1.0f);
#pragma unroll
    for (int e = 0; e < EPT; ++e) {
        const int idx = base + e * TPB;
        valid[e] = (idx < B);
        const float4 xv = valid[e] ? x[idx] : make_float4(0.f, 0.f, 0.f, 0.f);
        float c0, s0, c1, s1, c2, s2, c3, s3;
        __sincosf(xv.x, &s0, &c0);
        __sincosf(xv.y, &s1, &c1);
        __sincosf(xv.z, &s2, &c2);
        __sincosf(xv.w, &s3, &c3);
        const ull c0d = pk2(c0, c0), s0d = pk2(s0, s0);
        const ull c1d = pk2(c1, c1), s1d = pk2(s1, s1);
        const ull c2d = pk2(c2, c2), s2d = pk2(s2, s2);
        const ull c3d = pk2(c3, c3), s3d = pk2(s3, s3);
        p01[e][0] = ONE;  p01[e][1] = c1d; p01[e][2] = s1d;
        p01[e][3] = c0d;  p01[e][4] = mul2(c0d, c1d); p01[e][5] = mul2(c0d, s1d);
        p01[e][6] = s0d;  p01[e][7] = mul2(s0d, c1d); p01[e][8] = mul2(s0d, s1d);
        p23[e][0] = ONE;  p23[e][1] = c3d; p23[e][2] = s3d;
        p23[e][3] = c2d;  p23[e][4] = mul2(c2d, c3d); p23[e][5] = mul2(c2d, s3d);
        p23[e][6] = s2d;  p23[e][7] = mul2(s2d, c3d); p23[e][8] = mul2(s2d, s3d);
    }

    ull zlo[EPT], zhi[EPT];
#pragma unroll
    for (int e = 0; e < EPT; ++e) { zlo[e] = 0ull; zhi[e] = 0ull; }

    const ulonglong2* __restrict__ C2 = reinterpret_cast<const ulonglong2*>(shC);
#pragma unroll
    for (int u = 0; u < 9; ++u) {
        ull alo[EPT], ahi[EPT];
#pragma unroll
        for (int e = 0; e < EPT; ++e) { alo[e] = 0ull; ahi[e] = 0ull; }
#pragma unroll
        for (int v = 0; v < 9; ++v) {
            const ulonglong2 c = C2[u * 9 + v];   // LDS.128, warp-uniform bcast
#pragma unroll
            for (int e = 0; e < EPT; ++e) {
                alo[e] = fma2(c.x, p23[e][v], alo[e]);
                ahi[e] = fma2(c.y, p23[e][v], ahi[e]);
            }
        }
#pragma unroll
        for (int e = 0; e < EPT; ++e) {
            zlo[e] = fma2(alo[e], p01[e][u], zlo[e]);
            zhi[e] = fma2(ahi[e], p01[e][u], zhi[e]);
        }
    }

#pragma unroll
    for (int e = 0; e < EPT; ++e) {
        const int idx = base + e * TPB;
        if (valid[e]) {
            float z0, z1, z2, z3;
            upk2(zlo[e], z0, z1);
            upk2(zhi[e], z2, z3);
            out[idx] = make_float4(z0, z1, z2, z3);
        }
    }
}

// ---------------------------------------------------------------------------
extern "C" void kernel_launch(void* const* d_in, const int* in_sizes, int n_in,
                              void* d_out, int out_size) {
    int bx = 0, bw = 1;
    if (n_in >= 2 && in_sizes[0] == 60) { bx = 1; bw = 0; }
    const float* x   = (const float*)d_in[bx];
    const float* wts = (const float*)d_in[bw];
    const int B = in_sizes[bx] / 4;

    build_coeff_kernel<<<1, 352>>>(wts);
    const int grid = (B + TPB * EPT - 1) / (TPB * EPT);
    qforward_kernel<<<grid, TPB>>>((const float4*)x, (float4*)d_out, B);
}

// round 3
// speedup vs baseline: 2.2036x; 2.1767x over previous
#include <cuda_runtime.h>

// QuantumLayer: z_w(x) = sum_{u,v} C[w][u][v] * p01[u] * p23[v] over per-qubit
// features (1, cos x, sin x); C = f(weights) built once per launch.
// Kernel 1 (1 block, 256 thr): shuffle-parallel circuit unitary -> M_w -> C.
// Kernel 2: packed f32x2 trilinear evaluation, 180 FFMA2/element, single wave.

#define TPB 128
#define EPT 2

typedef unsigned long long ull;

__device__ float4 g_C[81];   // [u*9+v] -> (C_w0, C_w1, C_w2, C_w3)

__device__ __forceinline__ ull pk2(float lo, float hi) {
    ull r; asm("mov.b64 %0,{%1,%2};" : "=l"(r) : "f"(lo), "f"(hi)); return r;
}
__device__ __forceinline__ void upk2(ull a, float& lo, float& hi) {
    asm("mov.b64 {%0,%1},%2;" : "=f"(lo), "=f"(hi) : "l"(a));
}
__device__ __forceinline__ ull fma2(ull a, ull b, ull c) {
    ull d; asm("fma.rn.f32x2 %0,%1,%2,%3;" : "=l"(d) : "l"(a), "l"(b), "l"(c)); return d;
}
__device__ __forceinline__ ull mul2(ull a, ull b) {
    ull d; asm("mul.rn.f32x2 %0,%1,%2;" : "=l"(d) : "l"(a), "l"(b)); return d;
}

// ---------------------------------------------------------------------------
// Kernel 1: shuffle-parallel build of C. Thread tid = j*16 + i owns U[i][j].
// ---------------------------------------------------------------------------
__global__ void build_coeff_kernel(const float* __restrict__ weights) {
    __shared__ float sUr[16][16], sUi[16][16];
    __shared__ float sM[256 * 4];                // [(j*16+k)*4 + w]
    const int tid = threadIdx.x;
    const int i = tid & 15;                      // row (state index)

    // --- Stage 1: evolve identity through circuit; pair exchange via shfl ---
    float vr = (i == (tid >> 4)) ? 1.0f : 0.0f;
    float vi = 0.0f;

#pragma unroll
    for (int l = 0; l < 5; ++l) {
#pragma unroll
        for (int w = 0; w < 4; ++w) {
            const float phi   = __ldg(&weights[(l * 4 + w) * 3 + 0]);
            const float theta = __ldg(&weights[(l * 4 + w) * 3 + 1]);
            const float omega = __ldg(&weights[(l * 4 + w) * 3 + 2]);
            float sp, cp, sm, cm, st, ct;
            __sincosf(0.5f * (phi + omega), &sp, &cp);
            __sincosf(0.5f * (phi - omega), &sm, &cm);
            __sincosf(0.5f * theta, &st, &ct);
            const int m = 8 >> w;
            const float pr = __shfl_xor_sync(0xffffffffu, vr, m);
            const float pi = __shfl_xor_sync(0xffffffffu, vi, m);
            const bool bit = (i & m) != 0;
            // own-coefficient: r00 (bit=0) or r11 (bit=1); partner: r01 / r10
            const float cAr = cp * ct;
            const float cAi = bit ? sp * ct : -sp * ct;
            const float cBr = bit ? cm * st : -cm * st;
            const float cBi = -sm * st;
            const float nvr = cAr * vr - cAi * vi + cBr * pr - cBi * pi;
            const float nvi = cAr * vi + cAi * vr + cBr * pi + cBi * pr;
            vr = nvr; vi = nvi;
        }
        const int r = (l % 3) + 1;
#pragma unroll
        for (int w = 0; w < 4; ++w) {
            const int mc = 8 >> w;
            const int mt = 8 >> ((w + r) & 3);
            const float pr = __shfl_xor_sync(0xffffffffu, vr, mt);
            const float pi = __shfl_xor_sync(0xffffffffu, vi, mt);
            if (i & mc) { vr = pr; vi = pi; }
        }
    }
    sUr[i][tid >> 4] = vr;
    sUi[i][tid >> 4] = vi;
    __syncthreads();

    // --- Stage 2: M_w[j][k] = sum_i sign_w(i) Re(conj U_ij * U_ik) ---
    {
        const int j = tid >> 4, k = tid & 15;
        float m0 = 0.f, m1 = 0.f, m2 = 0.f, m3 = 0.f;
#pragma unroll
        for (int ii = 0; ii < 16; ++ii) {
            const float p = sUr[ii][j] * sUr[ii][k] + sUi[ii][j] * sUi[ii][k];
            m0 += (ii & 8) ? -p : p;
            m1 += (ii & 4) ? -p : p;
            m2 += (ii & 2) ? -p : p;
            m3 += (ii & 1) ? -p : p;
        }
        sM[tid * 4 + 0] = m0; sM[tid * 4 + 1] = m1;
        sM[tid * 4 + 2] = m2; sM[tid * 4 + 3] = m3;
    }
    __syncthreads();

    // --- Stage 3: project M_w onto (1, cos, sin)^{\otimes 4} basis ---
    if (tid < 81) {
        const int t0 = tid / 27, t1 = (tid / 9) % 3, t2 = (tid / 3) % 3, t3 = tid % 3;
        const int tt[4] = {t0, t1, t2, t3};
        float a0 = 0.f, a1 = 0.f, a2 = 0.f, a3 = 0.f;
#pragma unroll
        for (int b = 0; b < 16; ++b) {
            int j = 0, k = 0; float sgn = 1.0f;
#pragma unroll
            for (int q = 0; q < 4; ++q) {
                const int o = (b >> q) & 1;
                const int ti = tt[q];
                int jq, kq;
                if (ti == 2) { jq = o; kq = 1 - o; }
                else { jq = o; kq = o; if (ti == 1 && o) sgn = -sgn; }
                j = (j << 1) | jq;
                k = (k << 1) | kq;
            }
            const float* m = &sM[(j * 16 + k) * 4];
            a0 += sgn * m[0]; a1 += sgn * m[1];
            a2 += sgn * m[2]; a3 += sgn * m[3];
        }
        const int u = t0 * 3 + t1, v = t2 * 3 + t3;
        g_C[u * 9 + v] = make_float4(a0 * 0.0625f, a1 * 0.0625f,
                                     a2 * 0.0625f, a3 * 0.0625f);
    }
}

// ---------------------------------------------------------------------------
// Kernel 2: trilinear evaluation with packed outputs. Single-wave grid.
// ---------------------------------------------------------------------------
__global__ __launch_bounds__(TPB, 7)
void qforward_kernel(const float4* __restrict__ x, float4* __restrict__ out, int B) {
    __shared__ __align__(16) ull shC[162];       // [uv][{w01, w23}]
    if (threadIdx.x < 81) {
        const float4 c = g_C[threadIdx.x];
        shC[2 * threadIdx.x]     = pk2(c.x, c.y);
        shC[2 * threadIdx.x + 1] = pk2(c.z, c.w);
    }
    __syncthreads();

    const int base = blockIdx.x * (TPB * EPT) + threadIdx.x;

    ull p01[EPT][9], p23[EPT][9];
    bool valid[EPT];
    const ull ONE = pk2(1.0f, 1.0f);
#pragma unroll
    for (int e = 0; e < EPT; ++e) {
        const int idx = base + e * TPB;
        valid[e] = (idx < B);
        const float4 xv = valid[e] ? x[idx] : make_float4(0.f, 0.f, 0.f, 0.f);
        float c0, s0, c1, s1, c2, s2, c3, s3;
        __sincosf(xv.x, &s0, &c0);
        __sincosf(xv.y, &s1, &c1);
        __sincosf(xv.z, &s2, &c2);
        __sincosf(xv.w, &s3, &c3);
        const ull c0d = pk2(c0, c0), s0d = pk2(s0, s0);
        const ull c1d = pk2(c1, c1), s1d = pk2(s1, s1);
        const ull c2d = pk2(c2, c2), s2d = pk2(s2, s2);
        const ull c3d = pk2(c3, c3), s3d = pk2(s3, s3);
        p01[e][0] = ONE;  p01[e][1] = c1d; p01[e][2] = s1d;
        p01[e][3] = c0d;  p01[e][4] = mul2(c0d, c1d); p01[e][5] = mul2(c0d, s1d);
        p01[e][6] = s0d;  p01[e][7] = mul2(s0d, c1d); p01[e][8] = mul2(s0d, s1d);
        p23[e][0] = ONE;  p23[e][1] = c3d; p23[e][2] = s3d;
        p23[e][3] = c2d;  p23[e][4] = mul2(c2d, c3d); p23[e][5] = mul2(c2d, s3d);
        p23[e][6] = s2d;  p23[e][7] = mul2(s2d, c3d); p23[e][8] = mul2(s2d, s3d);
    }

    ull zlo[EPT], zhi[EPT];
#pragma unroll
    for (int e = 0; e < EPT; ++e) { zlo[e] = 0ull; zhi[e] = 0ull; }

    const ulonglong2* __restrict__ C2 = reinterpret_cast<const ulonglong2*>(shC);
#pragma unroll
    for (int u = 0; u < 9; ++u) {
        ull alo[EPT], ahi[EPT];
#pragma unroll
        for (int e = 0; e < EPT; ++e) { alo[e] = 0ull; ahi[e] = 0ull; }
#pragma unroll
        for (int v = 0; v < 9; ++v) {
            const ulonglong2 c = C2[u * 9 + v];   // LDS.128, warp-uniform bcast
#pragma unroll
            for (int e = 0; e < EPT; ++e) {
                alo[e] = fma2(c.x, p23[e][v], alo[e]);
                ahi[e] = fma2(c.y, p23[e][v], ahi[e]);
            }
        }
#pragma unroll
        for (int e = 0; e < EPT; ++e) {
            zlo[e] = fma2(alo[e], p01[e][u], zlo[e]);
            zhi[e] = fma2(ahi[e], p01[e][u], zhi[e]);
        }
    }

#pragma unroll
    for (int e = 0; e < EPT; ++e) {
        const int idx = base + e * TPB;
        if (valid[e]) {
            float z0, z1, z2, z3;
            upk2(zlo[e], z0, z1);
            upk2(zhi[e], z2, z3);
            out[idx] = make_float4(z0, z1, z2, z3);
        }
    }
}

// ---------------------------------------------------------------------------
extern "C" void kernel_launch(void* const* d_in, const int* in_sizes, int n_in,
                              void* d_out, int out_size) {
    int bx = 0, bw = 1;
    if (n_in >= 2 && in_sizes[0] == 60) { bx = 1; bw = 0; }
    const float* x   = (const float*)d_in[bx];
    const float* wts = (const float*)d_in[bw];
    const int B = in_sizes[bx] / 4;

    build_coeff_kernel<<<1, 256>>>(wts);
    const int grid = (B + TPB * EPT - 1) / (TPB * EPT);
    qforward_kernel<<<grid, TPB>>>((const float4*)x, (float4*)d_out, B);
}